// round 11
// baseline (speedup 1.0000x reference)
#include <cuda_runtime.h>

// EnhancedLesionPenaltyLoss: pred (16,1,128,128,128) fp32 -> scalar loss.
// KEY INSIGHT: kernel is LSU-request-bound (~2 LDG/cyc/SM ceiling), so halve
// the request count with 256-bit loads (ld.global.v8.f32, sm_100+).
// Each thread owns 8 consecutive floats (one 32B-aligned v8 load) per plane;
// h-neighbor row is a second v8 load (L1-resident). Request rate per work
// halves vs float4 version. Grid: 16 batches x 8 row-strips(16 rows) x
// 8 z-segments(16 slices) = 1024 blocks x 256 threads, (256,7) single wave.
// prev-plane kept in registers via double-buffer (no copies).
// Integer threshold compares + packed integer counters + integer max.
// Last block (atomic ticket) does the deterministic final reduction.

namespace {
constexpr int NB      = 16;
constexpr int STRIPS  = 8;               // 16-row strips per plane
constexpr int ZSEGS   = 8;               // 16 z-slices per segment
constexpr int ZLEN    = 16;
constexpr int NBLK    = NB * STRIPS * ZSEGS;   // 1024
constexpr int THREADS = 256;
constexpr int NACC    = 6;               // cmin,cmax,max,sds,s1,s2
constexpr unsigned U01 = 0x3C23D70Au;    // bits of 0.01f
constexpr unsigned U05 = 0x3F000000u;    // bits of 0.5f
}

__device__ float        g_part[NBLK * NACC];
__device__ unsigned int g_ticket = 0;

__device__ __forceinline__ void ldg256(float v[8], const char* p) {
    asm("ld.global.v8.f32 {%0,%1,%2,%3,%4,%5,%6,%7}, [%8];"
        : "=f"(v[0]), "=f"(v[1]), "=f"(v[2]), "=f"(v[3]),
          "=f"(v[4]), "=f"(v[5]), "=f"(v[6]), "=f"(v[7])
        : "l"(p));
}

struct St {
    unsigned cic;   // ci | (ch<<16)
    unsigned mxu;   // integer max (inputs non-negative)
    float sds, s1, s2;
};

__device__ __forceinline__ void iterbody(const float v[8], float prev[8],
                                         const char* pz, bool do_h, bool do_w,
                                         St& st) {
    // w-direction: 7 internal diffs + cross via shuffle of v[0].
    const float nx = __shfl_down_sync(0xffffffffu, v[0], 1);
    float g = 0.f;
#pragma unroll
    for (int k = 1; k < 8; ++k) g += fabsf(v[k] - v[k - 1]);
    if (do_w) g += fabsf(nx - v[7]);

    // h-direction: row+1 via one v8 load (L1-resident sibling data).
    if (do_h) {
        float h[8];
        ldg256(h, pz + 512);
#pragma unroll
        for (int k = 0; k < 8; ++k) g += fabsf(h[k] - v[k]);
    }
    // d-direction: prev plane in registers.
#pragma unroll
    for (int k = 0; k < 8; ++k) g += fabsf(v[k] - prev[k]);
    st.sds += g;

    // thresholds: integer compares (non-negative inputs), packed counters.
#pragma unroll
    for (int k = 0; k < 8; ++k) {
        const float    x  = v[k];
        const unsigned xu = __float_as_uint(x);
        if (xu > U01) {
            st.cic += 1u;
            st.s1  += x;
            st.s2   = fmaf(x, x, st.s2);
        }
        if (xu > U05) st.cic += 0x10000u;
        st.mxu = (xu > st.mxu) ? xu : st.mxu;
    }
}

__global__ __launch_bounds__(THREADS, 7)
void lesion_fused(const float* __restrict__ pred, float* __restrict__ out) {
    const int bid   = blockIdx.x;
    const int zseg  = bid & 7;
    const int strip = (bid >> 3) & 7;
    const int b     = bid >> 6;
    const int tid   = threadIdx.x;
    const int lane  = tid & 31;
    const int wid   = tid >> 5;

    const int col8 = tid & 15;             // 8-float column group (0..15)
    const int rloc = tid >> 4;             // row within strip (0..15)
    const int grow = strip * 16 + rloc;    // global row (0..127)
    const bool do_h = (grow < 127);
    const bool do_w = (col8 != 15);
    const int  z0   = zseg * ZLEN;

    // byte address of this thread's 8 floats at plane z0
    const char* pv = reinterpret_cast<const char*>(pred) +
                     (size_t)b * 8388608 + (size_t)z0 * 65536 +
                     (size_t)grow * 512 + (size_t)col8 * 32;

    St st = {0u, 0u, 0.f, 0.f, 0.f};

    float a[8], c[8];
    // seed prev: plane z0-1 (z0==0: plane z0 itself, self-diff = 0)
    ldg256(a, (z0 > 0) ? (pv - 65536) : pv);

    // double-buffered z-march: even iters load c (prev=a), odd load a (prev=c)
#pragma unroll 2
    for (int i = 0; i < ZLEN; i += 2) {
        const char* p0 = pv + (size_t)i * 65536;
        ldg256(c, p0);
        iterbody(c, a, p0, do_h, do_w, st);
        const char* p1 = p0 + 65536;
        ldg256(a, p1);
        iterbody(a, c, p1, do_h, do_w, st);
    }

    // ---- block reduction (8 warps) ----
    float acc[NACC] = {(float)(st.cic & 0xFFFFu), (float)(st.cic >> 16),
                       __uint_as_float(st.mxu), st.sds, st.s1, st.s2};
#pragma unroll
    for (int k = 0; k < NACC; ++k) {
#pragma unroll
        for (int off = 16; off; off >>= 1) {
            const float t = __shfl_xor_sync(0xffffffffu, acc[k], off);
            acc[k] = (k == 2) ? fmaxf(acc[k], t) : (acc[k] + t);
        }
    }
    __shared__ float red[8][NACC];
    __shared__ float fin[NB][NACC];
    __shared__ float lsh[NB];
    __shared__ unsigned int tick_sh;
    if (lane == 0) {
#pragma unroll
        for (int k = 0; k < NACC; ++k) red[wid][k] = acc[k];
    }
    __syncthreads();

    if (tid == 0) {
#pragma unroll
        for (int k = 0; k < NACC; ++k) {
            float r = red[0][k];
#pragma unroll
            for (int w = 1; w < 8; ++w)
                r = (k == 2) ? fmaxf(r, red[w][k]) : (r + red[w][k]);
            g_part[bid * NACC + k] = r;
        }
        __threadfence();
        tick_sh = atomicAdd(&g_ticket, 1u);
    }
    __syncthreads();
    if (tick_sh != (unsigned)(NBLK - 1)) return;

    // ---- last block: deterministic fixed-order final reduction ----
    __threadfence();  // acquire other blocks' g_part writes

    constexpr int PER_B = STRIPS * ZSEGS;  // 64 partials per batch
    if (tid < NB * NACC) {
        const int fb = tid / NACC;
        const int fk = tid % NACC;
        const float* base = &g_part[(fb * PER_B) * NACC + fk];
        float r = base[0];
#pragma unroll
        for (int c2 = 1; c2 < PER_B; ++c2) {
            const float t = base[c2 * NACC];
            r = (fk == 2) ? fmaxf(r, t) : (r + t);
        }
        fin[fb][fk] = r;
    }
    __syncthreads();

    if (tid < NB) {
        const float cnt   = fin[tid][0];
        const float chigh = fin[tid][1];
        const float mxv   = fin[tid][2];
        const float sg    = fin[tid][3];
        const float S1    = fin[tid][4];
        const float S2    = fin[tid][5];

        const float invN   = 1.f / 2097152.f;        // 1/128^3
        const float invND3 = 1.f / 6242304.f;        // 1/(3*127*128*128)

        const float act = cnt * invN;
        float loss = fmaxf(0.005f - act, 0.f) * 15.f;

        const float high = chigh * invN;
        loss += fmaxf(high - 0.03f, 0.f) * 5.f;

        const float avg_grad = sg * invND3;
        if (mxv > 0.3f) loss += fminf(avg_grad, 1.f) * 5.f;

        const float cnt_safe = fmaxf(cnt, 1.f);
        const float m  = S1 / cnt_safe;
        const float sq = fmaxf(S2 - 2.f * m * S1 + m * m * cnt, 0.f);
        const bool gate = (act > 0.001f) && (cnt > 1.f);
        const float var = gate ? (sq / fmaxf(cnt - 1.f, 1.f)) : 1.f;
        const float rel_std = sqrtf(var) / (m + 1e-6f);
        const float pen = expf(-5.f * rel_std);
        loss += (gate ? pen : 0.f) * 7.f;

        lsh[tid] = loss;
    }
    __syncthreads();
    if (tid == 0) {
        float t = 0.f;
#pragma unroll
        for (int i = 0; i < NB; ++i) t += lsh[i];
        out[0] = t * (1.f / 16.f);
        g_ticket = 0;  // reset for next (graph-replayed) launch
    }
}

extern "C" void kernel_launch(void* const* d_in, const int* in_sizes, int n_in,
                              void* d_out, int out_size) {
    (void)in_sizes; (void)n_in; (void)out_size;
    const float* pred = (const float*)d_in[0];
    float* out = (float*)d_out;
    lesion_fused<<<NBLK, THREADS>>>(pred, out);
}

// round 12
// speedup vs baseline: 1.7517x; 1.7517x over previous
#include <cuda_runtime.h>

// EnhancedLesionPenaltyLoss: pred (16,1,128,128,128) fp32 -> scalar loss.
// LSU-request-bound kernel (R6 measured at ~1.8 LDG/cyc/SM = issue floor).
// Fix: 256-bit loads (ld.global.v8.f32) halve the request count, THIS TIME
// with an adequate register budget: 512 blocks x 256 thr,
// __launch_bounds__(256,4) -> 64 regs/thread (R11 spilled at 32).
// 148*4=592 >= 512 -> single wave. Each thread owns 8 consecutive floats per
// plane, marches 32 z-slices; prev plane double-buffered in registers.
// Integer threshold compares + packed counters + integer max.
// Last block (atomic ticket) does the deterministic final reduction.

namespace {
constexpr int NB      = 16;
constexpr int STRIPS  = 8;               // 16-row strips per plane
constexpr int ZSEGS   = 4;               // 32 z-slices per segment
constexpr int ZLEN    = 32;
constexpr int NBLK    = NB * STRIPS * ZSEGS;   // 512
constexpr int THREADS = 256;
constexpr int NACC    = 6;               // cmin,cmax,max,sds,s1,s2
constexpr unsigned U01 = 0x3C23D70Au;    // bits of 0.01f
constexpr unsigned U05 = 0x3F000000u;    // bits of 0.5f
}

__device__ float        g_part[NBLK * NACC];
__device__ unsigned int g_ticket = 0;

__device__ __forceinline__ void ldg256(float v[8], const char* p) {
    asm("ld.global.v8.f32 {%0,%1,%2,%3,%4,%5,%6,%7}, [%8];"
        : "=f"(v[0]), "=f"(v[1]), "=f"(v[2]), "=f"(v[3]),
          "=f"(v[4]), "=f"(v[5]), "=f"(v[6]), "=f"(v[7])
        : "l"(p));
}

struct St {
    unsigned cic;   // ci | (ch<<16)
    unsigned mxu;   // integer max (inputs non-negative)
    float sds, s1, s2;
};

__device__ __forceinline__ void iterbody(const float v[8], const float prev[8],
                                         const char* pz, bool do_h, bool do_w,
                                         St& st) {
    // w-direction: 7 internal diffs + cross via shuffle of v[0].
    const float nx = __shfl_down_sync(0xffffffffu, v[0], 1);
    float g = 0.f;
#pragma unroll
    for (int k = 1; k < 8; ++k) g += fabsf(v[k] - v[k - 1]);
    if (do_w) g += fabsf(nx - v[7]);

    // h-direction: row+1 via one v8 load (L1-resident sibling data).
    if (do_h) {
        float h[8];
        ldg256(h, pz + 512);
#pragma unroll
        for (int k = 0; k < 8; ++k) g += fabsf(h[k] - v[k]);
    }
    // d-direction: prev plane in registers.
#pragma unroll
    for (int k = 0; k < 8; ++k) g += fabsf(v[k] - prev[k]);
    st.sds += g;

    // thresholds: integer compares (non-negative inputs), packed counters.
#pragma unroll
    for (int k = 0; k < 8; ++k) {
        const float    x  = v[k];
        const unsigned xu = __float_as_uint(x);
        if (xu > U01) {
            st.cic += 1u;
            st.s1  += x;
            st.s2   = fmaf(x, x, st.s2);
        }
        if (xu > U05) st.cic += 0x10000u;
        st.mxu = (xu > st.mxu) ? xu : st.mxu;
    }
}

__global__ __launch_bounds__(THREADS, 4)
void lesion_fused(const float* __restrict__ pred, float* __restrict__ out) {
    const int bid   = blockIdx.x;
    const int zseg  = bid & 3;
    const int strip = (bid >> 2) & 7;
    const int b     = bid >> 5;
    const int tid   = threadIdx.x;
    const int lane  = tid & 31;
    const int wid   = tid >> 5;

    const int col8 = tid & 15;             // 8-float column group (0..15)
    const int rloc = tid >> 4;             // row within strip (0..15)
    const int grow = strip * 16 + rloc;    // global row (0..127)
    const bool do_h = (grow < 127);
    const bool do_w = (col8 != 15);
    const int  z0   = zseg * ZLEN;

    // byte address of this thread's 8 floats at plane z0
    const char* pv = reinterpret_cast<const char*>(pred) +
                     (size_t)b * 8388608 + (size_t)z0 * 65536 +
                     (size_t)grow * 512 + (size_t)col8 * 32;

    St st = {0u, 0u, 0.f, 0.f, 0.f};

    float a[8], c[8];
    // seed prev: plane z0-1 (z0==0: plane z0 itself, self-diff = 0)
    ldg256(a, (z0 > 0) ? (pv - 65536) : pv);

    // double-buffered z-march: even iters load c (prev=a), odd load a (prev=c)
    for (int i = 0; i < ZLEN; i += 2) {
        const char* p0 = pv + (size_t)i * 65536;
        ldg256(c, p0);
        iterbody(c, a, p0, do_h, do_w, st);
        const char* p1 = p0 + 65536;
        ldg256(a, p1);
        iterbody(a, c, p1, do_h, do_w, st);
    }

    // ---- block reduction (8 warps) ----
    float acc[NACC] = {(float)(st.cic & 0xFFFFu), (float)(st.cic >> 16),
                       __uint_as_float(st.mxu), st.sds, st.s1, st.s2};
#pragma unroll
    for (int k = 0; k < NACC; ++k) {
#pragma unroll
        for (int off = 16; off; off >>= 1) {
            const float t = __shfl_xor_sync(0xffffffffu, acc[k], off);
            acc[k] = (k == 2) ? fmaxf(acc[k], t) : (acc[k] + t);
        }
    }
    __shared__ float red[8][NACC];
    __shared__ float fin[NB][NACC];
    __shared__ float lsh[NB];
    __shared__ unsigned int tick_sh;
    if (lane == 0) {
#pragma unroll
        for (int k = 0; k < NACC; ++k) red[wid][k] = acc[k];
    }
    __syncthreads();

    if (tid == 0) {
#pragma unroll
        for (int k = 0; k < NACC; ++k) {
            float r = red[0][k];
#pragma unroll
            for (int w = 1; w < 8; ++w)
                r = (k == 2) ? fmaxf(r, red[w][k]) : (r + red[w][k]);
            g_part[bid * NACC + k] = r;
        }
        __threadfence();
        tick_sh = atomicAdd(&g_ticket, 1u);
    }
    __syncthreads();
    if (tick_sh != (unsigned)(NBLK - 1)) return;

    // ---- last block: deterministic fixed-order final reduction ----
    __threadfence();  // acquire other blocks' g_part writes

    constexpr int PER_B = STRIPS * ZSEGS;  // 32 partials per batch
    if (tid < NB * NACC) {
        const int fb = tid / NACC;
        const int fk = tid % NACC;
        const float* base = &g_part[(fb * PER_B) * NACC + fk];
        float r = base[0];
#pragma unroll
        for (int c2 = 1; c2 < PER_B; ++c2) {
            const float t = base[c2 * NACC];
            r = (fk == 2) ? fmaxf(r, t) : (r + t);
        }
        fin[fb][fk] = r;
    }
    __syncthreads();

    if (tid < NB) {
        const float cnt   = fin[tid][0];
        const float chigh = fin[tid][1];
        const float mxv   = fin[tid][2];
        const float sg    = fin[tid][3];
        const float S1    = fin[tid][4];
        const float S2    = fin[tid][5];

        const float invN   = 1.f / 2097152.f;        // 1/128^3
        const float invND3 = 1.f / 6242304.f;        // 1/(3*127*128*128)

        const float act = cnt * invN;
        float loss = fmaxf(0.005f - act, 0.f) * 15.f;

        const float high = chigh * invN;
        loss += fmaxf(high - 0.03f, 0.f) * 5.f;

        const float avg_grad = sg * invND3;
        if (mxv > 0.3f) loss += fminf(avg_grad, 1.f) * 5.f;

        const float cnt_safe = fmaxf(cnt, 1.f);
        const float m  = S1 / cnt_safe;
        const float sq = fmaxf(S2 - 2.f * m * S1 + m * m * cnt, 0.f);
        const bool gate = (act > 0.001f) && (cnt > 1.f);
        const float var = gate ? (sq / fmaxf(cnt - 1.f, 1.f)) : 1.f;
        const float rel_std = sqrtf(var) / (m + 1e-6f);
        const float pen = expf(-5.f * rel_std);
        loss += (gate ? pen : 0.f) * 7.f;

        lsh[tid] = loss;
    }
    __syncthreads();
    if (tid == 0) {
        float t = 0.f;
#pragma unroll
        for (int i = 0; i < NB; ++i) t += lsh[i];
        out[0] = t * (1.f / 16.f);
        g_ticket = 0;  // reset for next (graph-replayed) launch
    }
}

extern "C" void kernel_launch(void* const* d_in, const int* in_sizes, int n_in,
                              void* d_out, int out_size) {
    (void)in_sizes; (void)n_in; (void)out_size;
    const float* pred = (const float*)d_in[0];
    float* out = (float*)d_out;
    lesion_fused<<<NBLK, THREADS>>>(pred, out);
}

// round 13
// speedup vs baseline: 1.8301x; 1.0448x over previous
#include <cuda_runtime.h>

// EnhancedLesionPenaltyLoss: pred (16,1,128,128,128) fp32 -> scalar loss.
// v8 loads (fewest requests+instrs) + copy-free rotating prefetch:
// 4 v-buffers / 2 h-buffers, unroll-4 -> all buffer indices compile-time.
// Each iter prefetches plane i+1 BEFORE processing plane i (load->use
// distance = one full body, ~100 instrs). prev plane = V[(i-1)&3], no copies.
// Grid: 16 x 8 strips(16 rows) x 4 zsegs(32 planes) = 512 blocks x 256 thr,
// __launch_bounds__(256,4) = 64-reg budget, single wave (592 >= 512).
// Integer threshold compares + packed counters + integer max.
// Last block (atomic ticket) does the deterministic final reduction.

namespace {
constexpr int NB      = 16;
constexpr int STRIPS  = 8;
constexpr int ZSEGS   = 4;
constexpr int ZLEN    = 32;
constexpr int NBLK    = NB * STRIPS * ZSEGS;   // 512
constexpr int THREADS = 256;
constexpr int NACC    = 6;               // cmin,cmax,max,sds,s1,s2
constexpr unsigned U01 = 0x3C23D70Au;    // bits of 0.01f
constexpr unsigned U05 = 0x3F000000u;    // bits of 0.5f
}

__device__ float        g_part[NBLK * NACC];
__device__ unsigned int g_ticket = 0;

__device__ __forceinline__ void ldg256(float v[8], const char* p) {
    asm("ld.global.v8.f32 {%0,%1,%2,%3,%4,%5,%6,%7}, [%8];"
        : "=f"(v[0]), "=f"(v[1]), "=f"(v[2]), "=f"(v[3]),
          "=f"(v[4]), "=f"(v[5]), "=f"(v[6]), "=f"(v[7])
        : "l"(p));
}

struct St {
    unsigned cic;   // ci | (ch<<16)
    unsigned mxu;   // integer max (inputs non-negative)
    float sds, s1, s2;
};

__device__ __forceinline__ void body(const float v[8], const float prev[8],
                                     const float h[8],
                                     bool do_h, bool do_w, St& st) {
    const float nx = __shfl_down_sync(0xffffffffu, v[0], 1);
    float g = 0.f;
#pragma unroll
    for (int k = 1; k < 8; ++k) g += fabsf(v[k] - v[k - 1]);
    if (do_w) g += fabsf(nx - v[7]);

    if (do_h) {
#pragma unroll
        for (int k = 0; k < 8; ++k) g += fabsf(h[k] - v[k]);
    }
#pragma unroll
    for (int k = 0; k < 8; ++k) g += fabsf(v[k] - prev[k]);
    st.sds += g;

#pragma unroll
    for (int k = 0; k < 8; ++k) {
        const float    x  = v[k];
        const unsigned xu = __float_as_uint(x);
        if (xu > U01) {
            st.cic += 1u;
            st.s1  += x;
            st.s2   = fmaf(x, x, st.s2);
        }
        if (xu > U05) st.cic += 0x10000u;
        st.mxu = (xu > st.mxu) ? xu : st.mxu;
    }
}

__global__ __launch_bounds__(THREADS, 4)
void lesion_fused(const float* __restrict__ pred, float* __restrict__ out) {
    const int bid   = blockIdx.x;
    const int zseg  = bid & 3;
    const int strip = (bid >> 2) & 7;
    const int b     = bid >> 5;
    const int tid   = threadIdx.x;
    const int lane  = tid & 31;
    const int wid   = tid >> 5;

    const int col8 = tid & 15;             // 8-float column group (0..15)
    const int rloc = tid >> 4;             // row within strip (0..15)
    const int grow = strip * 16 + rloc;    // global row (0..127)
    const bool do_h = (grow < 127);
    const bool do_w = (col8 != 15);
    const int  z0   = zseg * ZLEN;

    const char* pv = reinterpret_cast<const char*>(pred) +
                     (size_t)b * 8388608 + (size_t)z0 * 65536 +
                     (size_t)grow * 512 + (size_t)col8 * 32;

    St st = {0u, 0u, 0.f, 0.f, 0.f};

    float V[4][8];
    float H[2][8];

    // Seed: V[3] = prev plane (z0-1; z0==0 -> plane 0, self-diff = 0).
    ldg256(V[3], (z0 > 0) ? (pv - 65536) : pv);
    // Plane 0 v and h.
    ldg256(V[0], pv);
    if (do_h) ldg256(H[0], pv + 512);

    for (int i0 = 0; i0 < ZLEN; i0 += 4) {
#pragma unroll
        for (int k = 0; k < 4; ++k) {
            const int i  = i0 + k;
            const int zn = (i + 1 < ZLEN) ? (i + 1) : (ZLEN - 1); // clamp
            const char* pn = pv + (size_t)zn * 65536;

            // prefetch plane i+1 BEFORE processing plane i
            ldg256(V[(k + 1) & 3], pn);
            if (do_h) ldg256(H[(k + 1) & 1], pn + 512);

            body(V[k & 3], V[(k + 3) & 3], H[k & 1], do_h, do_w, st);
        }
    }

    // ---- block reduction (8 warps) ----
    float acc[NACC] = {(float)(st.cic & 0xFFFFu), (float)(st.cic >> 16),
                       __uint_as_float(st.mxu), st.sds, st.s1, st.s2};
#pragma unroll
    for (int k = 0; k < NACC; ++k) {
#pragma unroll
        for (int off = 16; off; off >>= 1) {
            const float t = __shfl_xor_sync(0xffffffffu, acc[k], off);
            acc[k] = (k == 2) ? fmaxf(acc[k], t) : (acc[k] + t);
        }
    }
    __shared__ float red[8][NACC];
    __shared__ float fin[NB][NACC];
    __shared__ float lsh[NB];
    __shared__ unsigned int tick_sh;
    if (lane == 0) {
#pragma unroll
        for (int k = 0; k < NACC; ++k) red[wid][k] = acc[k];
    }
    __syncthreads();

    if (tid == 0) {
#pragma unroll
        for (int k = 0; k < NACC; ++k) {
            float r = red[0][k];
#pragma unroll
            for (int w = 1; w < 8; ++w)
                r = (k == 2) ? fmaxf(r, red[w][k]) : (r + red[w][k]);
            g_part[bid * NACC + k] = r;
        }
        __threadfence();
        tick_sh = atomicAdd(&g_ticket, 1u);
    }
    __syncthreads();
    if (tick_sh != (unsigned)(NBLK - 1)) return;

    // ---- last block: deterministic fixed-order final reduction ----
    __threadfence();  // acquire other blocks' g_part writes

    constexpr int PER_B = STRIPS * ZSEGS;  // 32 partials per batch
    if (tid < NB * NACC) {
        const int fb = tid / NACC;
        const int fk = tid % NACC;
        const float* base = &g_part[(fb * PER_B) * NACC + fk];
        float r = base[0];
#pragma unroll
        for (int c2 = 1; c2 < PER_B; ++c2) {
            const float t = base[c2 * NACC];
            r = (fk == 2) ? fmaxf(r, t) : (r + t);
        }
        fin[fb][fk] = r;
    }
    __syncthreads();

    if (tid < NB) {
        const float cnt   = fin[tid][0];
        const float chigh = fin[tid][1];
        const float mxv   = fin[tid][2];
        const float sg    = fin[tid][3];
        const float S1    = fin[tid][4];
        const float S2    = fin[tid][5];

        const float invN   = 1.f / 2097152.f;        // 1/128^3
        const float invND3 = 1.f / 6242304.f;        // 1/(3*127*128*128)

        const float act = cnt * invN;
        float loss = fmaxf(0.005f - act, 0.f) * 15.f;

        const float high = chigh * invN;
        loss += fmaxf(high - 0.03f, 0.f) * 5.f;

        const float avg_grad = sg * invND3;
        if (mxv > 0.3f) loss += fminf(avg_grad, 1.f) * 5.f;

        const float cnt_safe = fmaxf(cnt, 1.f);
        const float m  = S1 / cnt_safe;
        const float sq = fmaxf(S2 - 2.f * m * S1 + m * m * cnt, 0.f);
        const bool gate = (act > 0.001f) && (cnt > 1.f);
        const float var = gate ? (sq / fmaxf(cnt - 1.f, 1.f)) : 1.f;
        const float rel_std = sqrtf(var) / (m + 1e-6f);
        const float pen = expf(-5.f * rel_std);
        loss += (gate ? pen : 0.f) * 7.f;

        lsh[tid] = loss;
    }
    __syncthreads();
    if (tid == 0) {
        float t = 0.f;
#pragma unroll
        for (int i = 0; i < NB; ++i) t += lsh[i];
        out[0] = t * (1.f / 16.f);
        g_ticket = 0;  // reset for next (graph-replayed) launch
    }
}

extern "C" void kernel_launch(void* const* d_in, const int* in_sizes, int n_in,
                              void* d_out, int out_size) {
    (void)in_sizes; (void)n_in; (void)out_size;
    const float* pred = (const float*)d_in[0];
    float* out = (float*)d_out;
    lesion_fused<<<NBLK, THREADS>>>(pred, out);
}